// round 1
// baseline (speedup 1.0000x reference)
#include <cuda_runtime.h>
#include <math.h>

// Problem constants
#define B_   4
#define L_   2048
#define D_   1024
#define H_   16
#define DK_  64
#define HD_  1024          // H*DK
#define MROWS_ 8192        // B*L
#define LN_EPS_ 1e-5f

// ---------------------------------------------------------------------------
// Scratch (device globals; no runtime allocation allowed)
// ---------------------------------------------------------------------------
__device__ float g_qh[MROWS_ * HD_];   // q projection  [B,L,H,DK]
__device__ float g_kh[MROWS_ * HD_];   // k projection
__device__ float g_vh[MROWS_ * HD_];   // v projection
__device__ float g_o [MROWS_ * HD_];   // attention output (pre o-proj)
__device__ float g_op[MROWS_ * HD_];   // after o-proj, pre-LN

// ---------------------------------------------------------------------------
// Generic NT GEMM:  C[z][M,N] = alpha * (A[z] @ B[z]^T) + bias
// A: [M,K] row-major (lda), Bm: [N,K] row-major (ldb), C: [M,N] (ldc)
// Batch offset: z -> (z/zdiv)*sXo + (z%zdiv)*sXi  (element strides)
// Tiles: 128x128x8, 256 threads, 8x8 micro-tile per thread.
// Requires M%128==0, N%128==0, K%8==0 (true for all uses here).
// ---------------------------------------------------------------------------
__global__ void __launch_bounds__(256)
sgemm_nt(const float* __restrict__ A, const float* __restrict__ Bm,
         const float* __restrict__ bias, float* __restrict__ C,
         int K, int lda, int ldb, int ldc, int zdiv,
         long long sAo, long long sAi,
         long long sBo, long long sBi,
         long long sCo, long long sCi,
         float alpha)
{
    const int z  = blockIdx.z;
    const int zo = z / zdiv;
    const int zi = z % zdiv;
    A  += zo * sAo + zi * sAi;
    Bm += zo * sBo + zi * sBi;
    C  += zo * sCo + zi * sCi;

    const int m0 = blockIdx.y * 128;
    const int n0 = blockIdx.x * 128;

    __shared__ float As[8][128];
    __shared__ float Bs[8][128];

    const int tid  = threadIdx.x;
    const int arow = tid >> 1;          // 0..127
    const int acol = (tid & 1) << 2;    // 0 or 4
    const int tx   = tid & 15;
    const int ty   = tid >> 4;

    const float* Ag = A  + (long long)(m0 + arow) * lda + acol;
    const float* Bg = Bm + (long long)(n0 + arow) * ldb + acol;

    float acc[8][8];
#pragma unroll
    for (int i = 0; i < 8; i++)
#pragma unroll
        for (int j = 0; j < 8; j++) acc[i][j] = 0.0f;

    for (int k0 = 0; k0 < K; k0 += 8) {
        float4 a4 = *(const float4*)(Ag + k0);
        float4 b4 = *(const float4*)(Bg + k0);
        __syncthreads();
        As[acol + 0][arow] = a4.x; As[acol + 1][arow] = a4.y;
        As[acol + 2][arow] = a4.z; As[acol + 3][arow] = a4.w;
        Bs[acol + 0][arow] = b4.x; Bs[acol + 1][arow] = b4.y;
        Bs[acol + 2][arow] = b4.z; Bs[acol + 3][arow] = b4.w;
        __syncthreads();
#pragma unroll
        for (int kk = 0; kk < 8; kk++) {
            float ra[8], rb[8];
#pragma unroll
            for (int i = 0; i < 8; i++) ra[i] = As[kk][ty * 8 + i];
#pragma unroll
            for (int j = 0; j < 8; j++) rb[j] = Bs[kk][tx * 8 + j];
#pragma unroll
            for (int i = 0; i < 8; i++)
#pragma unroll
                for (int j = 0; j < 8; j++)
                    acc[i][j] += ra[i] * rb[j];
        }
    }

    float bb[8];
    if (bias) {
#pragma unroll
        for (int j = 0; j < 8; j++) bb[j] = bias[n0 + tx * 8 + j];
    } else {
#pragma unroll
        for (int j = 0; j < 8; j++) bb[j] = 0.0f;
    }

#pragma unroll
    for (int i = 0; i < 8; i++) {
        const long long m = m0 + ty * 8 + i;
        float* Crow = C + m * (long long)ldc + n0 + tx * 8;
        float4 o0, o1;
        o0.x = acc[i][0] * alpha + bb[0];
        o0.y = acc[i][1] * alpha + bb[1];
        o0.z = acc[i][2] * alpha + bb[2];
        o0.w = acc[i][3] * alpha + bb[3];
        o1.x = acc[i][4] * alpha + bb[4];
        o1.y = acc[i][5] * alpha + bb[5];
        o1.z = acc[i][6] * alpha + bb[6];
        o1.w = acc[i][7] * alpha + bb[7];
        ((float4*)Crow)[0] = o0;
        ((float4*)Crow)[1] = o1;
    }
}

// ---------------------------------------------------------------------------
// In-place row softmax over rows of length L_ (=2048). One block per row.
// ---------------------------------------------------------------------------
__global__ void __launch_bounds__(256)
softmax_rows(float* __restrict__ attn)
{
    const long long row = blockIdx.x;
    float4* p4 = (float4*)(attn + row * (long long)L_);
    const int tid = threadIdx.x;

    float4 v0 = p4[tid];
    float4 v1 = p4[tid + 256];

    float m = fmaxf(fmaxf(fmaxf(v0.x, v0.y), fmaxf(v0.z, v0.w)),
                    fmaxf(fmaxf(v1.x, v1.y), fmaxf(v1.z, v1.w)));

    __shared__ float sred[8];
#pragma unroll
    for (int o = 16; o > 0; o >>= 1)
        m = fmaxf(m, __shfl_xor_sync(0xffffffffu, m, o));
    if ((tid & 31) == 0) sred[tid >> 5] = m;
    __syncthreads();
    m = fmaxf(fmaxf(fmaxf(sred[0], sred[1]), fmaxf(sred[2], sred[3])),
              fmaxf(fmaxf(sred[4], sred[5]), fmaxf(sred[6], sred[7])));

    v0.x = __expf(v0.x - m); v0.y = __expf(v0.y - m);
    v0.z = __expf(v0.z - m); v0.w = __expf(v0.w - m);
    v1.x = __expf(v1.x - m); v1.y = __expf(v1.y - m);
    v1.z = __expf(v1.z - m); v1.w = __expf(v1.w - m);

    float s = (v0.x + v0.y) + (v0.z + v0.w) + (v1.x + v1.y) + (v1.z + v1.w);
#pragma unroll
    for (int o = 16; o > 0; o >>= 1)
        s += __shfl_xor_sync(0xffffffffu, s, o);
    __syncthreads();               // protect sred reuse
    if ((tid & 31) == 0) sred[tid >> 5] = s;
    __syncthreads();
    s = (sred[0] + sred[1]) + (sred[2] + sred[3]) +
        (sred[4] + sred[5]) + (sred[6] + sred[7]);

    const float r = 1.0f / s;
    v0.x *= r; v0.y *= r; v0.z *= r; v0.w *= r;
    v1.x *= r; v1.y *= r; v1.z *= r; v1.w *= r;

    p4[tid]       = v0;
    p4[tid + 256] = v1;
}

// ---------------------------------------------------------------------------
// PV batched GEMM (NN):  O[b,:,h,:] = P[(h*B+b)] @ V[b,:,h,:]
// Per batch z = b*H + h:  M=L (q), N=DK (d), K=L (k).
// Tiles: 128(M) x 64(N) x 16(K), 256 threads, 8x4 micro-tile.
// ---------------------------------------------------------------------------
__global__ void __launch_bounds__(256)
pv_nn(const float* __restrict__ Pfull, const float* __restrict__ Vfull,
      float* __restrict__ Ofull)
{
    const int z = blockIdx.z;
    const int b = z >> 4;   // / H_
    const int h = z & 15;   // % H_

    const float* P = Pfull + ((long long)h * B_ + b) * (long long)L_ * L_;
    const float* V = Vfull + ((long long)b * L_) * HD_ + h * DK_;
    float*       O = Ofull + ((long long)b * L_) * HD_ + h * DK_;

    const int m0 = blockIdx.x * 128;

    __shared__ float Ps[16][128];  // k-major
    __shared__ float Vs[16][64];

    const int tid = threadIdx.x;
    const int tx  = tid & 15;
    const int ty  = tid >> 4;

    const int pq0 = tid >> 2;          // 0..63 (plus +64 for second half)
    const int pk0 = (tid & 3) << 2;    // 0,4,8,12
    const int vk  = tid >> 4;          // 0..15
    const int vc  = (tid & 15) << 2;   // 0..60

    float acc[8][4];
#pragma unroll
    for (int i = 0; i < 8; i++)
#pragma unroll
        for (int j = 0; j < 4; j++) acc[i][j] = 0.0f;

    for (int k0 = 0; k0 < L_; k0 += 16) {
        float4 pa = *(const float4*)(P + (long long)(m0 + pq0)      * L_ + k0 + pk0);
        float4 pb = *(const float4*)(P + (long long)(m0 + pq0 + 64) * L_ + k0 + pk0);
        float4 vv = *(const float4*)(V + (long long)(k0 + vk) * HD_ + vc);
        __syncthreads();
        Ps[pk0 + 0][pq0] = pa.x; Ps[pk0 + 1][pq0] = pa.y;
        Ps[pk0 + 2][pq0] = pa.z; Ps[pk0 + 3][pq0] = pa.w;
        Ps[pk0 + 0][pq0 + 64] = pb.x; Ps[pk0 + 1][pq0 + 64] = pb.y;
        Ps[pk0 + 2][pq0 + 64] = pb.z; Ps[pk0 + 3][pq0 + 64] = pb.w;
        *(float4*)&Vs[vk][vc] = vv;
        __syncthreads();
#pragma unroll
        for (int kk = 0; kk < 16; kk++) {
            float rp[8];
#pragma unroll
            for (int i = 0; i < 8; i++) rp[i] = Ps[kk][ty * 8 + i];
            float4 rv = *(const float4*)&Vs[kk][tx * 4];
#pragma unroll
            for (int i = 0; i < 8; i++) {
                acc[i][0] += rp[i] * rv.x;
                acc[i][1] += rp[i] * rv.y;
                acc[i][2] += rp[i] * rv.z;
                acc[i][3] += rp[i] * rv.w;
            }
        }
    }

#pragma unroll
    for (int i = 0; i < 8; i++) {
        float4 o = make_float4(acc[i][0], acc[i][1], acc[i][2], acc[i][3]);
        *(float4*)(O + (long long)(m0 + ty * 8 + i) * HD_ + tx * 4) = o;
    }
}

// ---------------------------------------------------------------------------
// LayerNorm (+ gamma/beta) + residual. One block per row of D_=1024.
// ---------------------------------------------------------------------------
__global__ void __launch_bounds__(256)
ln_residual(const float* __restrict__ x, const float* __restrict__ res,
            const float* __restrict__ gam, const float* __restrict__ bet,
            float* __restrict__ out)
{
    const long long row = blockIdx.x;
    const float4* x4 = (const float4*)(x   + row * D_);
    const float4* r4 = (const float4*)(res + row * D_);
    const int tid = threadIdx.x;

    float4 v = x4[tid];
    float s  = (v.x + v.y) + (v.z + v.w);
    float sq = (v.x * v.x + v.y * v.y) + (v.z * v.z + v.w * v.w);

#pragma unroll
    for (int o = 16; o > 0; o >>= 1) {
        s  += __shfl_xor_sync(0xffffffffu, s,  o);
        sq += __shfl_xor_sync(0xffffffffu, sq, o);
    }
    __shared__ float ss[8], sqs[8];
    if ((tid & 31) == 0) { ss[tid >> 5] = s; sqs[tid >> 5] = sq; }
    __syncthreads();
    s  = (ss[0]  + ss[1])  + (ss[2]  + ss[3])  + (ss[4]  + ss[5])  + (ss[6]  + ss[7]);
    sq = (sqs[0] + sqs[1]) + (sqs[2] + sqs[3]) + (sqs[4] + sqs[5]) + (sqs[6] + sqs[7]);

    const float mean = s * (1.0f / D_);
    float var = sq * (1.0f / D_) - mean * mean;
    var = fmaxf(var, 0.0f);
    const float rstd = rsqrtf(var + LN_EPS_);

    float4 g = ((const float4*)gam)[tid];
    float4 bt = ((const float4*)bet)[tid];
    float4 r = r4[tid];
    float4 o;
    o.x = (v.x - mean) * rstd * g.x + bt.x + r.x;
    o.y = (v.y - mean) * rstd * g.y + bt.y + r.y;
    o.z = (v.z - mean) * rstd * g.z + bt.z + r.z;
    o.w = (v.w - mean) * rstd * g.w + bt.w + r.w;
    ((float4*)(out + row * D_))[tid] = o;
}

// ---------------------------------------------------------------------------
// Launch
// ---------------------------------------------------------------------------
extern "C" void kernel_launch(void* const* d_in, const int* in_sizes, int n_in,
                              void* d_out, int out_size)
{
    (void)in_sizes; (void)n_in; (void)out_size;
    const float* q  = (const float*)d_in[0];
    const float* k  = (const float*)d_in[1];
    const float* v  = (const float*)d_in[2];
    const float* wq = (const float*)d_in[3];
    const float* bq = (const float*)d_in[4];
    const float* wk = (const float*)d_in[5];
    const float* bk = (const float*)d_in[6];
    const float* wv = (const float*)d_in[7];
    const float* bv = (const float*)d_in[8];
    const float* wo = (const float*)d_in[9];
    const float* bo = (const float*)d_in[10];
    const float* lg = (const float*)d_in[11];
    const float* lb = (const float*)d_in[12];

    float* out  = (float*)d_out;                              // [B,L,D]
    float* attn = out + (long long)B_ * L_ * D_;              // [H*B,L,L]

    float *qh, *kh, *vh, *oa, *op;
    cudaGetSymbolAddress((void**)&qh, g_qh);
    cudaGetSymbolAddress((void**)&kh, g_kh);
    cudaGetSymbolAddress((void**)&vh, g_vh);
    cudaGetSymbolAddress((void**)&oa, g_o);
    cudaGetSymbolAddress((void**)&op, g_op);

    dim3 blk(256);

    // QKV projections: [8192,1024] = X @ W^T + b
    dim3 gproj(HD_ / 128, MROWS_ / 128, 1);
    sgemm_nt<<<gproj, blk>>>(q, wq, bq, qh, D_, D_, D_, HD_, 1,
                             0, 0, 0, 0, 0, 0, 1.0f);
    sgemm_nt<<<gproj, blk>>>(k, wk, bk, kh, D_, D_, D_, HD_, 1,
                             0, 0, 0, 0, 0, 0, 1.0f);
    sgemm_nt<<<gproj, blk>>>(v, wv, bv, vh, D_, D_, D_, HD_, 1,
                             0, 0, 0, 0, 0, 0, 1.0f);

    // Scores: per (b,h): S[q,k] = (qh_bh @ kh_bh^T) / sqrt(DK), into attn[(h*B+b)]
    dim3 gsc(L_ / 128, L_ / 128, B_ * H_);
    sgemm_nt<<<gsc, blk>>>(qh, kh, nullptr, attn,
                           DK_, HD_, HD_, L_, H_,
                           (long long)L_ * HD_, (long long)DK_,     // A: b, h
                           (long long)L_ * HD_, (long long)DK_,     // B: b, h
                           (long long)L_ * L_, (long long)B_ * L_ * L_, // C: b, h
                           0.125f);

    // Softmax in place over attn rows
    softmax_rows<<<(unsigned)(B_ * H_ * L_), blk>>>(attn);

    // PV: O = P @ V
    pv_nn<<<dim3(L_ / 128, 1, B_ * H_), blk>>>(attn, vh, oa);

    // Output projection: [8192,1024] = O @ wo^T + bo
    sgemm_nt<<<gproj, blk>>>(oa, wo, bo, op, HD_, HD_, HD_, D_, 1,
                             0, 0, 0, 0, 0, 0, 1.0f);

    // LayerNorm + residual into out
    ln_residual<<<MROWS_, blk>>>(op, q, lg, lb, out);
}

// round 3
// speedup vs baseline: 1.7192x; 1.7192x over previous
#include <cuda_runtime.h>
#include <cuda_bf16.h>
#include <stdint.h>
#include <math.h>

#define B_   4
#define L_   2048
#define D_   1024
#define H_   16
#define DK_  64
#define HD_  1024
#define MROWS_ 8192
#define LN_EPS_ 1e-5f

// ---------------------------------------------------------------------------
// Scratch (device globals; no runtime allocation allowed)
// ---------------------------------------------------------------------------
__device__ float g_qh[MROWS_ * HD_];
__device__ float g_kh[MROWS_ * HD_];
__device__ float g_vh[MROWS_ * HD_];
__device__ float g_vT[(long long)B_ * H_ * DK_ * L_];
__device__ float g_o [MROWS_ * HD_];
__device__ float g_op[MROWS_ * HD_];

// ---------------------------------------------------------------------------
// helpers
// ---------------------------------------------------------------------------
__device__ __forceinline__ uint32_t smem_u32(const void* p) {
    uint32_t a;
    asm("{ .reg .u64 t; cvta.to.shared.u64 t, %1; cvt.u32.u64 %0, t; }" : "=r"(a) : "l"(p));
    return a;
}
__device__ __forceinline__ uint32_t sw128(uint32_t off) {
    return off ^ ((off >> 3) & 0x70);
}
#define LDSM_X4(r0, r1, r2, r3, addr)                                      \
    asm volatile("ldmatrix.sync.aligned.m8n8.x4.shared.b16 "               \
                 "{%0,%1,%2,%3}, [%4];"                                    \
                 : "=r"(r0), "=r"(r1), "=r"(r2), "=r"(r3) : "r"(addr))

__device__ __forceinline__ void mma16816(float* d, const uint32_t* a, const uint32_t* b) {
    asm volatile(
        "mma.sync.aligned.m16n8k16.row.col.f32.bf16.bf16.f32 "
        "{%0,%1,%2,%3}, {%4,%5,%6,%7}, {%8,%9}, {%0,%1,%2,%3};"
        : "+f"(d[0]), "+f"(d[1]), "+f"(d[2]), "+f"(d[3])
        : "r"(a[0]), "r"(a[1]), "r"(a[2]), "r"(a[3]), "r"(b[0]), "r"(b[1]));
}

// split fp32x4 -> hi/lo bf16x4; row is 128B: [hi 64B | lo 64B], swizzled
__device__ __forceinline__ void split_store4(char* base, int row, int c4, float4 v) {
    __nv_bfloat162 h0 = __floats2bfloat162_rn(v.x, v.y);
    __nv_bfloat162 h1 = __floats2bfloat162_rn(v.z, v.w);
    float2 f0 = __bfloat1622float2(h0);
    float2 f1 = __bfloat1622float2(h1);
    __nv_bfloat162 l0 = __floats2bfloat162_rn(v.x - f0.x, v.y - f0.y);
    __nv_bfloat162 l1 = __floats2bfloat162_rn(v.z - f1.x, v.w - f1.y);
    uint2 hu, lu;
    hu.x = *(uint32_t*)&h0; hu.y = *(uint32_t*)&h1;
    lu.x = *(uint32_t*)&l0; lu.y = *(uint32_t*)&l1;
    uint32_t offh = sw128((uint32_t)(row * 128 + c4 * 8));
    uint32_t offl = sw128((uint32_t)(row * 128 + 64 + c4 * 8));
    *(uint2*)(base + offh) = hu;
    *(uint2*)(base + offl) = lu;
}

// ---------------------------------------------------------------------------
// HMMA split-bf16 GEMM:  C[z][128 x TN] = alpha * (A[z] @ B[z]^T) + bias
// A: [M,K] row-major (lda), B: [N,K] row-major (ldb). K % 32 == 0.
// Batch offsets: z -> (z/zdiv)*sXo + (z%zdiv)*sXi.
// 8 warps as WM x WN grid; warp tile (128/WM) x (TN/WN).
// ---------------------------------------------------------------------------
template<int TN, int WM, int WN>
__global__ void __launch_bounds__(256)
hmma_gemm(const float* __restrict__ A, const float* __restrict__ Bm,
          const float* __restrict__ bias, float* __restrict__ C,
          int K, int lda, int ldb, int ldc, int zdiv,
          long long sAo, long long sAi,
          long long sBo, long long sBi,
          long long sCo, long long sCi,
          float alpha)
{
    constexpr int MT = 128 / WM / 16;   // m16 tiles per warp
    constexpr int NT = TN / WN / 8;     // n8  tiles per warp
    constexpr int NB = TN / 32;         // B float4 loads per thread per chunk

    __shared__ __align__(128) char sA[128 * 128];     // 128 rows x (64B hi | 64B lo)
    __shared__ __align__(128) char sB[TN * 128];
    __shared__ float s_bias[TN];

    const int tid  = threadIdx.x;
    const int wid  = tid >> 5;
    const int lane = tid & 31;

    const int z  = blockIdx.z;
    const int zo = z / zdiv;
    const int zi = z - zo * zdiv;
    A  += zo * sAo + zi * sAi;
    Bm += zo * sBo + zi * sBi;
    C  += zo * sCo + zi * sCi;

    const long long m0 = (long long)blockIdx.y * 128;
    const long long n0 = (long long)blockIdx.x * TN;

    const int wm = (wid % WM) * (128 / WM);
    const int wn = (wid / WM) * (TN / WN);

    if (tid < TN) s_bias[tid] = bias ? bias[n0 + tid] : 0.0f;

    float acc[MT][NT][4];
#pragma unroll
    for (int i = 0; i < MT; i++)
#pragma unroll
        for (int j = 0; j < NT; j++)
#pragma unroll
            for (int e = 0; e < 4; e++) acc[i][j][e] = 0.0f;

    const uint32_t aS = smem_u32(sA);
    const uint32_t bS = smem_u32(sB);

    // precomputed ldmatrix offsets (per lane)
    const uint32_t a_row = (uint32_t)((lane & 7) + (lane & 8));
    const uint32_t a_kof = (uint32_t)(((lane >> 4) & 1) * 16);
    const uint32_t b_row = (uint32_t)((lane & 7) + ((lane >> 4) & 1) * 8);
    const uint32_t b_kof = (uint32_t)(((lane >> 3) & 1) * 16);

    float4 ra[4], rb[NB];
    // prefetch chunk 0
#pragma unroll
    for (int i = 0; i < 4; i++) {
        const int idx = i * 256 + tid;
        ra[i] = *(const float4*)(A + (m0 + (idx >> 3)) * (long long)lda + (idx & 7) * 4);
    }
#pragma unroll
    for (int i = 0; i < NB; i++) {
        const int idx = i * 256 + tid;
        rb[i] = *(const float4*)(Bm + (n0 + (idx >> 3)) * (long long)ldb + (idx & 7) * 4);
    }

    for (int k0 = 0; k0 < K; k0 += 32) {
        __syncthreads();   // previous chunk's math done
#pragma unroll
        for (int i = 0; i < 4; i++) {
            const int idx = i * 256 + tid;
            split_store4(sA, idx >> 3, idx & 7, ra[i]);
        }
#pragma unroll
        for (int i = 0; i < NB; i++) {
            const int idx = i * 256 + tid;
            split_store4(sB, idx >> 3, idx & 7, rb[i]);
        }
        __syncthreads();

        if (k0 + 32 < K) {   // prefetch next chunk (overlaps math below)
#pragma unroll
            for (int i = 0; i < 4; i++) {
                const int idx = i * 256 + tid;
                ra[i] = *(const float4*)(A + (m0 + (idx >> 3)) * (long long)lda + k0 + 32 + (idx & 7) * 4);
            }
#pragma unroll
            for (int i = 0; i < NB; i++) {
                const int idx = i * 256 + tid;
                rb[i] = *(const float4*)(Bm + (n0 + (idx >> 3)) * (long long)ldb + k0 + 32 + (idx & 7) * 4);
            }
        }

#pragma unroll
        for (int ks = 0; ks < 2; ks++) {
            uint32_t ah[MT][4], al[MT][4], bh[NT][2], bl[NT][2];
#pragma unroll
            for (int mt = 0; mt < MT; mt++) {
                uint32_t off = (uint32_t)(wm + mt * 16 + a_row) * 128 + ks * 32 + a_kof;
                LDSM_X4(ah[mt][0], ah[mt][1], ah[mt][2], ah[mt][3], aS + sw128(off));
            }
#pragma unroll
            for (int p = 0; p < NT / 2; p++) {
                uint32_t r0, r1, r2, r3;
                uint32_t off = (uint32_t)(wn + p * 16 + b_row) * 128 + ks * 32 + b_kof;
                LDSM_X4(r0, r1, r2, r3, bS + sw128(off));
                bh[2 * p][0] = r0; bh[2 * p][1] = r1;
                bh[2 * p + 1][0] = r2; bh[2 * p + 1][1] = r3;
            }
#pragma unroll
            for (int mt = 0; mt < MT; mt++)
#pragma unroll
                for (int nt = 0; nt < NT; nt++)
                    mma16816(acc[mt][nt], ah[mt], bh[nt]);

#pragma unroll
            for (int p = 0; p < NT / 2; p++) {
                uint32_t r0, r1, r2, r3;
                uint32_t off = (uint32_t)(wn + p * 16 + b_row) * 128 + 64 + ks * 32 + b_kof;
                LDSM_X4(r0, r1, r2, r3, bS + sw128(off));
                bl[2 * p][0] = r0; bl[2 * p][1] = r1;
                bl[2 * p + 1][0] = r2; bl[2 * p + 1][1] = r3;
            }
#pragma unroll
            for (int mt = 0; mt < MT; mt++)
#pragma unroll
                for (int nt = 0; nt < NT; nt++)
                    mma16816(acc[mt][nt], ah[mt], bl[nt]);

#pragma unroll
            for (int mt = 0; mt < MT; mt++) {
                uint32_t off = (uint32_t)(wm + mt * 16 + a_row) * 128 + 64 + ks * 32 + a_kof;
                LDSM_X4(al[mt][0], al[mt][1], al[mt][2], al[mt][3], aS + sw128(off));
            }
#pragma unroll
            for (int mt = 0; mt < MT; mt++)
#pragma unroll
                for (int nt = 0; nt < NT; nt++)
                    mma16816(acc[mt][nt], al[mt], bh[nt]);
        }
    }

    // epilogue
    const int g = lane >> 2;
    const int t = lane & 3;
#pragma unroll
    for (int mt = 0; mt < MT; mt++) {
#pragma unroll
        for (int nt = 0; nt < NT; nt++) {
            const int colw = wn + nt * 8 + 2 * t;
            const float bb0 = s_bias[colw];
            const float bb1 = s_bias[colw + 1];
            const long long row0 = m0 + wm + mt * 16 + g;
            float2 o0, o1;
            o0.x = acc[mt][nt][0] * alpha + bb0;
            o0.y = acc[mt][nt][1] * alpha + bb1;
            o1.x = acc[mt][nt][2] * alpha + bb0;
            o1.y = acc[mt][nt][3] * alpha + bb1;
            *(float2*)(C + row0 * (long long)ldc + n0 + colw) = o0;
            *(float2*)(C + (row0 + 8) * (long long)ldc + n0 + colw) = o1;
        }
    }
}

// ---------------------------------------------------------------------------
// V transpose: vh [B,L,H,DK] -> vT [B,H,DK,L]
// ---------------------------------------------------------------------------
__global__ void __launch_bounds__(256)
transpose_v(const float* __restrict__ vh, float* __restrict__ vT)
{
    __shared__ float tsm[32][33];
    const int bh = blockIdx.z;
    const int b = bh >> 4, h = bh & 15;
    const int l0 = blockIdx.x * 32;
    const int d0 = blockIdx.y * 32;
    const int tx = threadIdx.x & 31;
    const int ty = threadIdx.x >> 5;

    const float* src = vh + ((long long)b * L_ + l0) * HD_ + h * DK_ + d0;
#pragma unroll
    for (int i = 0; i < 32; i += 8)
        tsm[ty + i][tx] = src[(long long)(ty + i) * HD_ + tx];
    __syncthreads();
    float* dst = vT + (((long long)b * H_ + h) * DK_ + d0) * L_ + l0;
#pragma unroll
    for (int i = 0; i < 32; i += 8)
        dst[(long long)(ty + i) * L_ + tx] = tsm[tx][ty + i];
}

// ---------------------------------------------------------------------------
// In-place row softmax, rows of length L_=2048. One block per row.
// ---------------------------------------------------------------------------
__global__ void __launch_bounds__(256)
softmax_rows(float* __restrict__ attn)
{
    const long long row = blockIdx.x;
    float4* p4 = (float4*)(attn + row * (long long)L_);
    const int tid = threadIdx.x;

    float4 v0 = p4[tid];
    float4 v1 = p4[tid + 256];

    float m = fmaxf(fmaxf(fmaxf(v0.x, v0.y), fmaxf(v0.z, v0.w)),
                    fmaxf(fmaxf(v1.x, v1.y), fmaxf(v1.z, v1.w)));
    __shared__ float sred[8];
#pragma unroll
    for (int o = 16; o > 0; o >>= 1)
        m = fmaxf(m, __shfl_xor_sync(0xffffffffu, m, o));
    if ((tid & 31) == 0) sred[tid >> 5] = m;
    __syncthreads();
    m = fmaxf(fmaxf(fmaxf(sred[0], sred[1]), fmaxf(sred[2], sred[3])),
              fmaxf(fmaxf(sred[4], sred[5]), fmaxf(sred[6], sred[7])));

    v0.x = __expf(v0.x - m); v0.y = __expf(v0.y - m);
    v0.z = __expf(v0.z - m); v0.w = __expf(v0.w - m);
    v1.x = __expf(v1.x - m); v1.y = __expf(v1.y - m);
    v1.z = __expf(v1.z - m); v1.w = __expf(v1.w - m);

    float s = (v0.x + v0.y) + (v0.z + v0.w) + (v1.x + v1.y) + (v1.z + v1.w);
#pragma unroll
    for (int o = 16; o > 0; o >>= 1)
        s += __shfl_xor_sync(0xffffffffu, s, o);
    __syncthreads();
    if ((tid & 31) == 0) sred[tid >> 5] = s;
    __syncthreads();
    s = (sred[0] + sred[1]) + (sred[2] + sred[3]) +
        (sred[4] + sred[5]) + (sred[6] + sred[7]);

    const float r = 1.0f / s;
    v0.x *= r; v0.y *= r; v0.z *= r; v0.w *= r;
    v1.x *= r; v1.y *= r; v1.z *= r; v1.w *= r;
    p4[tid]       = v0;
    p4[tid + 256] = v1;
}

// ---------------------------------------------------------------------------
// LayerNorm + residual
// ---------------------------------------------------------------------------
__global__ void __launch_bounds__(256)
ln_residual(const float* __restrict__ x, const float* __restrict__ res,
            const float* __restrict__ gam, const float* __restrict__ bet,
            float* __restrict__ out)
{
    const long long row = blockIdx.x;
    const float4* x4 = (const float4*)(x   + row * D_);
    const float4* r4 = (const float4*)(res + row * D_);
    const int tid = threadIdx.x;

    float4 v = x4[tid];
    float s  = (v.x + v.y) + (v.z + v.w);
    float sq = (v.x * v.x + v.y * v.y) + (v.z * v.z + v.w * v.w);
#pragma unroll
    for (int o = 16; o > 0; o >>= 1) {
        s  += __shfl_xor_sync(0xffffffffu, s,  o);
        sq += __shfl_xor_sync(0xffffffffu, sq, o);
    }
    __shared__ float ss[8], sqs[8];
    if ((tid & 31) == 0) { ss[tid >> 5] = s; sqs[tid >> 5] = sq; }
    __syncthreads();
    s  = (ss[0]  + ss[1])  + (ss[2]  + ss[3])  + (ss[4]  + ss[5])  + (ss[6]  + ss[7]);
    sq = (sqs[0] + sqs[1]) + (sqs[2] + sqs[3]) + (sqs[4] + sqs[5]) + (sqs[6] + sqs[7]);

    const float mean = s * (1.0f / D_);
    float var = sq * (1.0f / D_) - mean * mean;
    var = fmaxf(var, 0.0f);
    const float rstd = rsqrtf(var + LN_EPS_);

    float4 g  = ((const float4*)gam)[tid];
    float4 bt = ((const float4*)bet)[tid];
    float4 r  = r4[tid];
    float4 o;
    o.x = (v.x - mean) * rstd * g.x + bt.x + r.x;
    o.y = (v.y - mean) * rstd * g.y + bt.y + r.y;
    o.z = (v.z - mean) * rstd * g.z + bt.z + r.z;
    o.w = (v.w - mean) * rstd * g.w + bt.w + r.w;
    ((float4*)(out + row * D_))[tid] = o;
}

// ---------------------------------------------------------------------------
// Launch
// ---------------------------------------------------------------------------
extern "C" void kernel_launch(void* const* d_in, const int* in_sizes, int n_in,
                              void* d_out, int out_size)
{
    (void)in_sizes; (void)n_in; (void)out_size;
    const float* q  = (const float*)d_in[0];
    const float* k  = (const float*)d_in[1];
    const float* v  = (const float*)d_in[2];
    const float* wq = (const float*)d_in[3];
    const float* bq = (const float*)d_in[4];
    const float* wk = (const float*)d_in[5];
    const float* bk = (const float*)d_in[6];
    const float* wv = (const float*)d_in[7];
    const float* bv = (const float*)d_in[8];
    const float* wo = (const float*)d_in[9];
    const float* bo = (const float*)d_in[10];
    const float* lg = (const float*)d_in[11];
    const float* lb = (const float*)d_in[12];

    float* out  = (float*)d_out;
    float* attn = out + (long long)B_ * L_ * D_;

    float *qh, *kh, *vh, *vT, *oa, *op;
    cudaGetSymbolAddress((void**)&qh, g_qh);
    cudaGetSymbolAddress((void**)&kh, g_kh);
    cudaGetSymbolAddress((void**)&vh, g_vh);
    cudaGetSymbolAddress((void**)&vT, g_vT);
    cudaGetSymbolAddress((void**)&oa, g_o);
    cudaGetSymbolAddress((void**)&op, g_op);

    dim3 blk(256);

    // QKV projections: [8192,1024] = X @ W^T + b
    dim3 gproj(HD_ / 128, MROWS_ / 128, 1);
    hmma_gemm<128, 2, 4><<<gproj, blk>>>(q, wq, bq, qh, D_, D_, D_, HD_, 1,
                                         0, 0, 0, 0, 0, 0, 1.0f);
    hmma_gemm<128, 2, 4><<<gproj, blk>>>(k, wk, bk, kh, D_, D_, D_, HD_, 1,
                                         0, 0, 0, 0, 0, 0, 1.0f);
    hmma_gemm<128, 2, 4><<<gproj, blk>>>(v, wv, bv, vh, D_, D_, D_, HD_, 1,
                                         0, 0, 0, 0, 0, 0, 1.0f);

    // V transpose for PV NT form
    transpose_v<<<dim3(L_ / 32, DK_ / 32, B_ * H_), blk>>>(vh, vT);

    // Scores: per z=b*H+h: attn[(h*B+b)] = (qh_bh @ kh_bh^T) / 8
    dim3 gsc(L_ / 128, L_ / 128, B_ * H_);
    hmma_gemm<128, 2, 4><<<gsc, blk>>>(qh, kh, nullptr, attn,
                                       DK_, HD_, HD_, L_, H_,
                                       (long long)L_ * HD_, (long long)DK_,
                                       (long long)L_ * HD_, (long long)DK_,
                                       (long long)L_ * L_, (long long)B_ * L_ * L_,
                                       0.125f);

    // Softmax in place
    softmax_rows<<<(unsigned)(B_ * H_ * L_), blk>>>(attn);

    // PV: O[b,:,h,:] = P[(h*B+b)] @ vT[b,h]^T
    dim3 gpv(1, L_ / 128, B_ * H_);
    hmma_gemm<64, 4, 2><<<gpv, blk>>>(attn, vT, nullptr, oa,
                                      L_, L_, L_, HD_, H_,
                                      (long long)L_ * L_, (long long)B_ * L_ * L_,
                                      (long long)H_ * DK_ * L_, (long long)DK_ * L_,
                                      (long long)L_ * HD_, (long long)DK_,
                                      1.0f);

    // Output projection
    hmma_gemm<128, 2, 4><<<gproj, blk>>>(oa, wo, bo, op, HD_, HD_, HD_, D_, 1,
                                         0, 0, 0, 0, 0, 0, 1.0f);

    // LayerNorm + residual
    ln_residual<<<MROWS_, blk>>>(op, q, lg, lb, out);
}

// round 4
// speedup vs baseline: 1.9561x; 1.1378x over previous
#include <cuda_runtime.h>
#include <cuda_bf16.h>
#include <stdint.h>
#include <math.h>

#define B_   4
#define L_   2048
#define D_   1024
#define H_   16
#define DK_  64
#define HD_  1024
#define MROWS_ 8192
#define LN_EPS_ 1e-5f
#define NROWS_ATTN (B_ * H_ * L_)

// ---------------------------------------------------------------------------
// Scratch (device globals; no runtime allocation allowed)
// ---------------------------------------------------------------------------
__device__ float g_qh[MROWS_ * HD_];
__device__ float g_kh[MROWS_ * HD_];
__device__ float g_vh[MROWS_ * HD_];
__device__ float g_vT[(long long)B_ * H_ * DK_ * L_];
__device__ float g_o [MROWS_ * HD_];
__device__ float g_op[MROWS_ * HD_];
__device__ float g_rs[NROWS_ATTN];       // softmax row sums

// ---------------------------------------------------------------------------
// helpers
// ---------------------------------------------------------------------------
__device__ __forceinline__ uint32_t smem_u32(const void* p) {
    uint32_t a;
    asm("{ .reg .u64 t; cvta.to.shared.u64 t, %1; cvt.u32.u64 %0, t; }" : "=r"(a) : "l"(p));
    return a;
}
__device__ __forceinline__ uint32_t sw128(uint32_t off) {
    return off ^ ((off >> 3) & 0x70);
}
#define LDSM_X4(r0, r1, r2, r3, addr)                                      \
    asm volatile("ldmatrix.sync.aligned.m8n8.x4.shared.b16 "               \
                 "{%0,%1,%2,%3}, [%4];"                                    \
                 : "=r"(r0), "=r"(r1), "=r"(r2), "=r"(r3) : "r"(addr))

__device__ __forceinline__ void mma16816(float* d, const uint32_t* a, const uint32_t* b) {
    asm volatile(
        "mma.sync.aligned.m16n8k16.row.col.f32.bf16.bf16.f32 "
        "{%0,%1,%2,%3}, {%4,%5,%6,%7}, {%8,%9}, {%0,%1,%2,%3};"
        : "+f"(d[0]), "+f"(d[1]), "+f"(d[2]), "+f"(d[3])
        : "r"(a[0]), "r"(a[1]), "r"(a[2]), "r"(a[3]), "r"(b[0]), "r"(b[1]));
}

// split fp32x4 -> hi/lo bf16x4; row is 128B: [hi 64B | lo 64B], swizzled
__device__ __forceinline__ void split_store4(char* base, int row, int c4, float4 v) {
    __nv_bfloat162 h0 = __floats2bfloat162_rn(v.x, v.y);
    __nv_bfloat162 h1 = __floats2bfloat162_rn(v.z, v.w);
    float2 f0 = __bfloat1622float2(h0);
    float2 f1 = __bfloat1622float2(h1);
    __nv_bfloat162 l0 = __floats2bfloat162_rn(v.x - f0.x, v.y - f0.y);
    __nv_bfloat162 l1 = __floats2bfloat162_rn(v.z - f1.x, v.w - f1.y);
    uint2 hu, lu;
    hu.x = *(uint32_t*)&h0; hu.y = *(uint32_t*)&h1;
    lu.x = *(uint32_t*)&l0; lu.y = *(uint32_t*)&l1;
    uint32_t offh = sw128((uint32_t)(row * 128 + c4 * 8));
    uint32_t offl = sw128((uint32_t)(row * 128 + 64 + c4 * 8));
    *(uint2*)(base + offh) = hu;
    *(uint2*)(base + offl) = lu;
}

// ---------------------------------------------------------------------------
// HMMA split-bf16 GEMM:  C[z][128 x TN] = alpha * (A[z] @ B[z]^T) + bias
// EXP_OUT: C = exp(alpha*acc); accumulate row sums into rs (atomics).
// NORM_A:  A values scaled by 1/rs[row] during staging; normalized values
//          also written back to Aw (in-place attn normalization).
// Double-buffered smem, one barrier per 32-K chunk.
// ---------------------------------------------------------------------------
template<int TN, int WM, int WN, bool EXP_OUT, bool NORM_A>
__global__ void __launch_bounds__(256)
hmma_gemm(const float* __restrict__ A, float* __restrict__ Aw,
          const float* __restrict__ Bm,
          const float* __restrict__ bias, float* __restrict__ C,
          float* __restrict__ rs, long long rsO, long long rsI,
          int K, int lda, int ldb, int ldc, int zdiv,
          long long sAo, long long sAi,
          long long sBo, long long sBi,
          long long sCo, long long sCi,
          float alpha)
{
    constexpr int MT = 128 / WM / 16;
    constexpr int NT = TN / WN / 8;
    constexpr int NB = TN / 32;
    constexpr int ABYTES = 128 * 128;
    constexpr int BBYTES = TN * 128;

    extern __shared__ char dsm_raw[];
    __shared__ float s_bias[TN > 128 ? TN : 128];
    __shared__ float s_aux[128];   // EXP_OUT: row sums; NORM_A: 1/rowsum

    const int tid  = threadIdx.x;
    const int wid  = tid >> 5;
    const int lane = tid & 31;

    const int z  = blockIdx.z;
    const int zo = z / zdiv;
    const int zi = z - zo * zdiv;
    A  += zo * sAo + zi * sAi;
    if (NORM_A) Aw += zo * sAo + zi * sAi;
    Bm += zo * sBo + zi * sBi;
    C  += zo * sCo + zi * sCi;
    const long long rs_off = zo * rsO + zi * rsI;

    const long long m0 = (long long)blockIdx.y * 128;
    const long long n0 = (long long)blockIdx.x * TN;

    // align dynamic smem to 1KB
    uint32_t raw32 = smem_u32(dsm_raw);
    uint32_t base32 = (raw32 + 1023u) & ~1023u;
    char* dsm = dsm_raw + (base32 - raw32);
    char* sA[2] = { dsm, dsm + ABYTES };
    char* sB[2] = { dsm + 2 * ABYTES, dsm + 2 * ABYTES + BBYTES };
    const uint32_t aSb[2] = { base32, base32 + ABYTES };
    const uint32_t bSb[2] = { base32 + 2 * ABYTES, base32 + 2 * ABYTES + BBYTES };

    const int wm = (wid % WM) * (128 / WM);
    const int wn = (wid / WM) * (TN / WN);

    if (!EXP_OUT) { if (tid < TN) s_bias[tid] = bias ? bias[n0 + tid] : 0.0f; }
    if (EXP_OUT)  { if (tid < 128) s_aux[tid] = 0.0f; }
    if (NORM_A)   { if (tid < 128) s_aux[tid] = 1.0f / rs[rs_off + m0 + tid]; }
    if (NORM_A || EXP_OUT) __syncthreads();

    float acc[MT][NT][4];
#pragma unroll
    for (int i = 0; i < MT; i++)
#pragma unroll
        for (int j = 0; j < NT; j++)
#pragma unroll
            for (int e = 0; e < 4; e++) acc[i][j][e] = 0.0f;

    const uint32_t a_row = (uint32_t)((lane & 7) + (lane & 8));
    const uint32_t a_kof = (uint32_t)(((lane >> 4) & 1) * 16);
    const uint32_t b_row = (uint32_t)((lane & 7) + ((lane >> 4) & 1) * 8);
    const uint32_t b_kof = (uint32_t)(((lane >> 3) & 1) * 16);

    float4 ra[4], rb[NB];

    // ---- preamble: chunk 0 ----
#pragma unroll
    for (int i = 0; i < 4; i++) {
        const int idx = i * 256 + tid;
        ra[i] = *(const float4*)(A + (m0 + (idx >> 3)) * (long long)lda + (idx & 7) * 4);
    }
#pragma unroll
    for (int i = 0; i < NB; i++) {
        const int idx = i * 256 + tid;
        rb[i] = *(const float4*)(Bm + (n0 + (idx >> 3)) * (long long)ldb + (idx & 7) * 4);
    }
#pragma unroll
    for (int i = 0; i < 4; i++) {
        const int idx = i * 256 + tid;
        float4 v = ra[i];
        if (NORM_A) {
            const float inv = s_aux[idx >> 3];
            v.x *= inv; v.y *= inv; v.z *= inv; v.w *= inv;
            *(float4*)(Aw + (m0 + (idx >> 3)) * (long long)lda + (idx & 7) * 4) = v;
        }
        split_store4(sA[0], idx >> 3, idx & 7, v);
    }
#pragma unroll
    for (int i = 0; i < NB; i++) {
        const int idx = i * 256 + tid;
        split_store4(sB[0], idx >> 3, idx & 7, rb[i]);
    }
    __syncthreads();

    int cur = 0;
    for (int k0 = 0; k0 < K; k0 += 32) {
        const bool has_next = (k0 + 32 < K);
        if (has_next) {
#pragma unroll
            for (int i = 0; i < 4; i++) {
                const int idx = i * 256 + tid;
                ra[i] = *(const float4*)(A + (m0 + (idx >> 3)) * (long long)lda + k0 + 32 + (idx & 7) * 4);
            }
#pragma unroll
            for (int i = 0; i < NB; i++) {
                const int idx = i * 256 + tid;
                rb[i] = *(const float4*)(Bm + (n0 + (idx >> 3)) * (long long)ldb + k0 + 32 + (idx & 7) * 4);
            }
        }

        const uint32_t aS = aSb[cur];
        const uint32_t bS = bSb[cur];
#pragma unroll
        for (int ks = 0; ks < 2; ks++) {
            uint32_t ah[MT][4], al[MT][4], bh[NT][2], bl[NT][2];
#pragma unroll
            for (int mt = 0; mt < MT; mt++) {
                uint32_t off = (uint32_t)(wm + mt * 16 + a_row) * 128 + ks * 32 + a_kof;
                LDSM_X4(ah[mt][0], ah[mt][1], ah[mt][2], ah[mt][3], aS + sw128(off));
            }
#pragma unroll
            for (int p = 0; p < NT / 2; p++) {
                uint32_t r0, r1, r2, r3;
                uint32_t off = (uint32_t)(wn + p * 16 + b_row) * 128 + ks * 32 + b_kof;
                LDSM_X4(r0, r1, r2, r3, bS + sw128(off));
                bh[2 * p][0] = r0; bh[2 * p][1] = r1;
                bh[2 * p + 1][0] = r2; bh[2 * p + 1][1] = r3;
            }
#pragma unroll
            for (int mt = 0; mt < MT; mt++)
#pragma unroll
                for (int nt = 0; nt < NT; nt++)
                    mma16816(acc[mt][nt], ah[mt], bh[nt]);

#pragma unroll
            for (int p = 0; p < NT / 2; p++) {
                uint32_t r0, r1, r2, r3;
                uint32_t off = (uint32_t)(wn + p * 16 + b_row) * 128 + 64 + ks * 32 + b_kof;
                LDSM_X4(r0, r1, r2, r3, bS + sw128(off));
                bl[2 * p][0] = r0; bl[2 * p][1] = r1;
                bl[2 * p + 1][0] = r2; bl[2 * p + 1][1] = r3;
            }
#pragma unroll
            for (int mt = 0; mt < MT; mt++)
#pragma unroll
                for (int nt = 0; nt < NT; nt++)
                    mma16816(acc[mt][nt], ah[mt], bl[nt]);

#pragma unroll
            for (int mt = 0; mt < MT; mt++) {
                uint32_t off = (uint32_t)(wm + mt * 16 + a_row) * 128 + 64 + ks * 32 + a_kof;
                LDSM_X4(al[mt][0], al[mt][1], al[mt][2], al[mt][3], aS + sw128(off));
            }
#pragma unroll
            for (int mt = 0; mt < MT; mt++)
#pragma unroll
                for (int nt = 0; nt < NT; nt++)
                    mma16816(acc[mt][nt], al[mt], bh[nt]);
        }

        if (has_next) {
            const int nxt = cur ^ 1;
#pragma unroll
            for (int i = 0; i < 4; i++) {
                const int idx = i * 256 + tid;
                float4 v = ra[i];
                if (NORM_A) {
                    const float inv = s_aux[idx >> 3];
                    v.x *= inv; v.y *= inv; v.z *= inv; v.w *= inv;
                    *(float4*)(Aw + (m0 + (idx >> 3)) * (long long)lda + k0 + 32 + (idx & 7) * 4) = v;
                }
                split_store4(sA[nxt], idx >> 3, idx & 7, v);
            }
#pragma unroll
            for (int i = 0; i < NB; i++) {
                const int idx = i * 256 + tid;
                split_store4(sB[nxt], idx >> 3, idx & 7, rb[i]);
            }
        }
        __syncthreads();
        cur ^= 1;
    }

    // ---- epilogue ----
    const int g = lane >> 2;
    const int t = lane & 3;
    if (EXP_OUT) {
#pragma unroll
        for (int mt = 0; mt < MT; mt++) {
            float sum0 = 0.0f, sum1 = 0.0f;
#pragma unroll
            for (int nt = 0; nt < NT; nt++) {
                const int colw = wn + nt * 8 + 2 * t;
                const long long row0 = m0 + wm + mt * 16 + g;
                float e0 = __expf(acc[mt][nt][0] * alpha);
                float e1 = __expf(acc[mt][nt][1] * alpha);
                float e2 = __expf(acc[mt][nt][2] * alpha);
                float e3 = __expf(acc[mt][nt][3] * alpha);
                *(float2*)(C + row0 * (long long)ldc + n0 + colw) = make_float2(e0, e1);
                *(float2*)(C + (row0 + 8) * (long long)ldc + n0 + colw) = make_float2(e2, e3);
                sum0 += e0 + e1;
                sum1 += e2 + e3;
            }
            // reduce over the 4 lanes sharing a row (t = 0..3)
            sum0 += __shfl_xor_sync(0xffffffffu, sum0, 1);
            sum0 += __shfl_xor_sync(0xffffffffu, sum0, 2);
            sum1 += __shfl_xor_sync(0xffffffffu, sum1, 1);
            sum1 += __shfl_xor_sync(0xffffffffu, sum1, 2);
            if (t == 0) {
                atomicAdd(&s_aux[wm + mt * 16 + g], sum0);
                atomicAdd(&s_aux[wm + mt * 16 + g + 8], sum1);
            }
        }
        __syncthreads();
        if (tid < 128)
            atomicAdd(&rs[rs_off + m0 + tid], s_aux[tid]);
    } else {
#pragma unroll
        for (int mt = 0; mt < MT; mt++) {
#pragma unroll
            for (int nt = 0; nt < NT; nt++) {
                const int colw = wn + nt * 8 + 2 * t;
                const float bb0 = s_bias[colw];
                const float bb1 = s_bias[colw + 1];
                const long long row0 = m0 + wm + mt * 16 + g;
                float2 o0, o1;
                o0.x = acc[mt][nt][0] * alpha + bb0;
                o0.y = acc[mt][nt][1] * alpha + bb1;
                o1.x = acc[mt][nt][2] * alpha + bb0;
                o1.y = acc[mt][nt][3] * alpha + bb1;
                *(float2*)(C + row0 * (long long)ldc + n0 + colw) = o0;
                *(float2*)(C + (row0 + 8) * (long long)ldc + n0 + colw) = o1;
            }
        }
    }
}

// ---------------------------------------------------------------------------
// V transpose: vh [B,L,H,DK] -> vT [B,H,DK,L]
// ---------------------------------------------------------------------------
__global__ void __launch_bounds__(256)
transpose_v(const float* __restrict__ vh, float* __restrict__ vT)
{
    __shared__ float tsm[32][33];
    const int bh = blockIdx.z;
    const int b = bh >> 4, h = bh & 15;
    const int l0 = blockIdx.x * 32;
    const int d0 = blockIdx.y * 32;
    const int tx = threadIdx.x & 31;
    const int ty = threadIdx.x >> 5;

    const float* src = vh + ((long long)b * L_ + l0) * HD_ + h * DK_ + d0;
#pragma unroll
    for (int i = 0; i < 32; i += 8)
        tsm[ty + i][tx] = src[(long long)(ty + i) * HD_ + tx];
    __syncthreads();
    float* dst = vT + (((long long)b * H_ + h) * DK_ + d0) * L_ + l0;
#pragma unroll
    for (int i = 0; i < 32; i += 8)
        dst[(long long)(ty + i) * L_ + tx] = tsm[tx][ty + i];
}

// ---------------------------------------------------------------------------
// zero the rowsum array
// ---------------------------------------------------------------------------
__global__ void zero_rs(float* __restrict__ rs)
{
    rs[blockIdx.x * 256 + threadIdx.x] = 0.0f;
}

// ---------------------------------------------------------------------------
// LayerNorm + residual
// ---------------------------------------------------------------------------
__global__ void __launch_bounds__(256)
ln_residual(const float* __restrict__ x, const float* __restrict__ res,
            const float* __restrict__ gam, const float* __restrict__ bet,
            float* __restrict__ out)
{
    const long long row = blockIdx.x;
    const float4* x4 = (const float4*)(x   + row * D_);
    const float4* r4 = (const float4*)(res + row * D_);
    const int tid = threadIdx.x;

    float4 v = x4[tid];
    float s  = (v.x + v.y) + (v.z + v.w);
    float sq = (v.x * v.x + v.y * v.y) + (v.z * v.z + v.w * v.w);
#pragma unroll
    for (int o = 16; o > 0; o >>= 1) {
        s  += __shfl_xor_sync(0xffffffffu, s,  o);
        sq += __shfl_xor_sync(0xffffffffu, sq, o);
    }
    __shared__ float ss[8], sqs[8];
    if ((tid & 31) == 0) { ss[tid >> 5] = s; sqs[tid >> 5] = sq; }
    __syncthreads();
    s  = (ss[0]  + ss[1])  + (ss[2]  + ss[3])  + (ss[4]  + ss[5])  + (ss[6]  + ss[7]);
    sq = (sqs[0] + sqs[1]) + (sqs[2] + sqs[3]) + (sqs[4] + sqs[5]) + (sqs[6] + sqs[7]);

    const float mean = s * (1.0f / D_);
    float var = sq * (1.0f / D_) - mean * mean;
    var = fmaxf(var, 0.0f);
    const float rstd = rsqrtf(var + LN_EPS_);

    float4 g  = ((const float4*)gam)[tid];
    float4 bt = ((const float4*)bet)[tid];
    float4 r  = r4[tid];
    float4 o;
    o.x = (v.x - mean) * rstd * g.x + bt.x + r.x;
    o.y = (v.y - mean) * rstd * g.y + bt.y + r.y;
    o.z = (v.z - mean) * rstd * g.z + bt.z + r.z;
    o.w = (v.w - mean) * rstd * g.w + bt.w + r.w;
    ((float4*)(out + row * D_))[tid] = o;
}

// ---------------------------------------------------------------------------
// Launch
// ---------------------------------------------------------------------------
extern "C" void kernel_launch(void* const* d_in, const int* in_sizes, int n_in,
                              void* d_out, int out_size)
{
    (void)in_sizes; (void)n_in; (void)out_size;
    const float* q  = (const float*)d_in[0];
    const float* k  = (const float*)d_in[1];
    const float* v  = (const float*)d_in[2];
    const float* wq = (const float*)d_in[3];
    const float* bq = (const float*)d_in[4];
    const float* wk = (const float*)d_in[5];
    const float* bk = (const float*)d_in[6];
    const float* wv = (const float*)d_in[7];
    const float* bv = (const float*)d_in[8];
    const float* wo = (const float*)d_in[9];
    const float* bo = (const float*)d_in[10];
    const float* lg = (const float*)d_in[11];
    const float* lb = (const float*)d_in[12];

    float* out  = (float*)d_out;
    float* attn = out + (long long)B_ * L_ * D_;

    float *qh, *kh, *vh, *vT, *oa, *op, *rs;
    cudaGetSymbolAddress((void**)&qh, g_qh);
    cudaGetSymbolAddress((void**)&kh, g_kh);
    cudaGetSymbolAddress((void**)&vh, g_vh);
    cudaGetSymbolAddress((void**)&vT, g_vT);
    cudaGetSymbolAddress((void**)&oa, g_o);
    cudaGetSymbolAddress((void**)&op, g_op);
    cudaGetSymbolAddress((void**)&rs, g_rs);

    const int SM128 = 2 * (128 * 128) + 2 * (128 * 128) + 1024;  // 66560
    const int SM64  = 2 * (128 * 128) + 2 * (64 * 128) + 1024;   // 50176
    cudaFuncSetAttribute((const void*)hmma_gemm<128, 2, 4, false, false>,
                         cudaFuncAttributeMaxDynamicSharedMemorySize, SM128);
    cudaFuncSetAttribute((const void*)hmma_gemm<128, 2, 4, true, false>,
                         cudaFuncAttributeMaxDynamicSharedMemorySize, SM128);
    cudaFuncSetAttribute((const void*)hmma_gemm<64, 4, 2, false, true>,
                         cudaFuncAttributeMaxDynamicSharedMemorySize, SM64);

    dim3 blk(256);

    zero_rs<<<NROWS_ATTN / 256, blk>>>(rs);

    // QKV projections
    dim3 gproj(HD_ / 128, MROWS_ / 128, 1);
    hmma_gemm<128, 2, 4, false, false><<<gproj, blk, SM128>>>(
        q, nullptr, wq, bq, qh, nullptr, 0, 0,
        D_, D_, D_, HD_, 1, 0, 0, 0, 0, 0, 0, 1.0f);
    hmma_gemm<128, 2, 4, false, false><<<gproj, blk, SM128>>>(
        k, nullptr, wk, bk, kh, nullptr, 0, 0,
        D_, D_, D_, HD_, 1, 0, 0, 0, 0, 0, 0, 1.0f);
    hmma_gemm<128, 2, 4, false, false><<<gproj, blk, SM128>>>(
        v, nullptr, wv, bv, vh, nullptr, 0, 0,
        D_, D_, D_, HD_, 1, 0, 0, 0, 0, 0, 0, 1.0f);

    transpose_v<<<dim3(L_ / 32, DK_ / 32, B_ * H_), blk>>>(vh, vT);

    // Scores + exp + rowsum: attn[(h*B+b)] = exp((qh@kh^T)/8)  (unnormalized)
    dim3 gsc(L_ / 128, L_ / 128, B_ * H_);
    hmma_gemm<128, 2, 4, true, false><<<gsc, blk, SM128>>>(
        qh, nullptr, kh, nullptr, attn, rs, (long long)L_, (long long)B_ * L_,
        DK_, HD_, HD_, L_, H_,
        (long long)L_ * HD_, (long long)DK_,
        (long long)L_ * HD_, (long long)DK_,
        (long long)L_ * L_, (long long)B_ * L_ * L_,
        0.125f);

    // PV with in-place attn normalization: O = (P/rowsum) @ vT^T; attn /= rowsum
    dim3 gpv(1, L_ / 128, B_ * H_);
    hmma_gemm<64, 4, 2, false, true><<<gpv, blk, SM64>>>(
        attn, attn, vT, nullptr, oa, rs, (long long)L_, (long long)B_ * L_,
        L_, L_, L_, HD_, H_,
        (long long)L_ * L_, (long long)B_ * L_ * L_,
        (long long)H_ * DK_ * L_, (long long)DK_ * L_,
        (long long)L_ * HD_, (long long)DK_,
        1.0f);

    // Output projection
    hmma_gemm<128, 2, 4, false, false><<<gproj, blk, SM128>>>(
        oa, nullptr, wo, bo, op, nullptr, 0, 0,
        HD_, HD_, HD_, D_, 1, 0, 0, 0, 0, 0, 0, 1.0f);

    // LayerNorm + residual
    ln_residual<<<MROWS_, blk>>>(op, q, lg, lb, out);
}

// round 5
// speedup vs baseline: 2.2202x; 1.1350x over previous
#include <cuda_runtime.h>
#include <cuda_bf16.h>
#include <stdint.h>

#define B_   4
#define L_   2048
#define D_   1024
#define H_   16
#define DK_  64
#define HD_  1024
#define MROWS_ 8192
#define LN_EPS_ 1e-5f
#define NROWS_ATTN (B_ * H_ * L_)

// ---------------------------------------------------------------------------
// Scratch (device globals; no runtime allocation allowed)
// Packed split-bf16 layout: [M][K/32][32 hi bf16 | 32 lo bf16]  (128B per chunk)
// ---------------------------------------------------------------------------
__device__ __align__(256) uint8_t g_qpk [(long long)MROWS_ * D_ * 4];
__device__ __align__(256) uint8_t g_kpk [(long long)MROWS_ * D_ * 4];
__device__ __align__(256) uint8_t g_vpk [(long long)MROWS_ * D_ * 4];
__device__ __align__(256) uint8_t g_wqpk[(long long)HD_ * D_ * 4];
__device__ __align__(256) uint8_t g_wkpk[(long long)HD_ * D_ * 4];
__device__ __align__(256) uint8_t g_wvpk[(long long)HD_ * D_ * 4];
__device__ __align__(256) uint8_t g_wopk[(long long)D_ * HD_ * 4];
__device__ __align__(256) uint8_t g_qhpk[(long long)MROWS_ * HD_ * 4];
__device__ __align__(256) uint8_t g_khpk[(long long)MROWS_ * HD_ * 4];
__device__ __align__(256) uint8_t g_vTpk[(long long)B_ * H_ * DK_ * L_ * 4];
__device__ __align__(256) uint8_t g_oapk[(long long)MROWS_ * HD_ * 4];
__device__ float g_vh[MROWS_ * HD_];
__device__ float g_op[MROWS_ * HD_];
__device__ float g_rs[NROWS_ATTN];

// ---------------------------------------------------------------------------
// helpers
// ---------------------------------------------------------------------------
__device__ __forceinline__ uint32_t smem_u32(const void* p) {
    uint32_t a;
    asm("{ .reg .u64 t; cvta.to.shared.u64 t, %1; cvt.u32.u64 %0, t; }" : "=r"(a) : "l"(p));
    return a;
}
__device__ __forceinline__ uint32_t sw128(uint32_t off) {
    return off ^ ((off >> 3) & 0x70);
}
__device__ __forceinline__ void cpa16(uint32_t dst, const void* src) {
    asm volatile("cp.async.cg.shared.global [%0], [%1], 16;" :: "r"(dst), "l"(src));
}
#define LDSM_X4(r0, r1, r2, r3, addr)                                      \
    asm volatile("ldmatrix.sync.aligned.m8n8.x4.shared.b16 "               \
                 "{%0,%1,%2,%3}, [%4];"                                    \
                 : "=r"(r0), "=r"(r1), "=r"(r2), "=r"(r3) : "r"(addr))

__device__ __forceinline__ void mma16816(float* d, const uint32_t* a, const uint32_t* b) {
    asm volatile(
        "mma.sync.aligned.m16n8k16.row.col.f32.bf16.bf16.f32 "
        "{%0,%1,%2,%3}, {%4,%5,%6,%7}, {%8,%9}, {%0,%1,%2,%3};"
        : "+f"(d[0]), "+f"(d[1]), "+f"(d[2]), "+f"(d[3])
        : "r"(a[0]), "r"(a[1]), "r"(a[2]), "r"(a[3]), "r"(b[0]), "r"(b[1]));
}

// pack 2 fp32 -> hi bf162 at p, lo bf162 at p+64
__device__ __forceinline__ void pack_store2(uint8_t* p, float v0, float v1) {
    __nv_bfloat162 h = __floats2bfloat162_rn(v0, v1);
    float2 f = __bfloat1622float2(h);
    __nv_bfloat162 l = __floats2bfloat162_rn(v0 - f.x, v1 - f.y);
    *(uint32_t*)p = *(uint32_t*)&h;
    *(uint32_t*)(p + 64) = *(uint32_t*)&l;
}
// pack 4 fp32 -> 8B hi at p, 8B lo at p+64
__device__ __forceinline__ void pack_store4(uint8_t* p, float4 v) {
    __nv_bfloat162 h0 = __floats2bfloat162_rn(v.x, v.y);
    __nv_bfloat162 h1 = __floats2bfloat162_rn(v.z, v.w);
    float2 f0 = __bfloat1622float2(h0), f1 = __bfloat1622float2(h1);
    __nv_bfloat162 l0 = __floats2bfloat162_rn(v.x - f0.x, v.y - f0.y);
    __nv_bfloat162 l1 = __floats2bfloat162_rn(v.z - f1.x, v.w - f1.y);
    uint2 hu, lu;
    hu.x = *(uint32_t*)&h0; hu.y = *(uint32_t*)&h1;
    lu.x = *(uint32_t*)&l0; lu.y = *(uint32_t*)&l1;
    *(uint2*)p = hu;
    *(uint2*)(p + 64) = lu;
}
__device__ __forceinline__ void combine8(const uint4 h, const uint4 l, float inv, float* out) {
    const uint32_t hu[4] = { h.x, h.y, h.z, h.w };
    const uint32_t lu[4] = { l.x, l.y, l.z, l.w };
#pragma unroll
    for (int j = 0; j < 4; j++) {
        __nv_bfloat162 hb = *(const __nv_bfloat162*)&hu[j];
        __nv_bfloat162 lb = *(const __nv_bfloat162*)&lu[j];
        float2 hf = __bfloat1622float2(hb), lf = __bfloat1622float2(lb);
        out[2 * j]     = (hf.x + lf.x) * inv;
        out[2 * j + 1] = (hf.y + lf.y) * inv;
    }
}

// ---------------------------------------------------------------------------
// pack fp32 [M,K] -> packed split bf16
// ---------------------------------------------------------------------------
__global__ void __launch_bounds__(256)
pack_split(const float* __restrict__ src, uint8_t* __restrict__ dst, int K)
{
    const long long idx = (long long)blockIdx.x * 256 + threadIdx.x;  // float4 id
    const int perRow = K >> 2;
    const long long m = idx / perRow;
    const int j = (int)(idx - m * perRow);
    float4 v = *(const float4*)(src + m * K + j * 4);
    const int e0 = j * 4;
    uint8_t* p = dst + (m * (K >> 5) + (e0 >> 5)) * 128 + (e0 & 31) * 2;
    pack_store4(p, v);
}

// ---------------------------------------------------------------------------
// Packed split-bf16 GEMM. 128x64 tile, 8 warps (2x4), 2 CTAs/SM.
// MODE 0: C fp32 + bias.  MODE 1: C packed + bias.
// MODE 2: exp(alpha*acc) -> packed + rowsum atomics.
// MODE 3: A staged tiles -> normalized fp32 P write (in-place); epilogue
//         scales acc by 1/rowsum -> packed out.
// ---------------------------------------------------------------------------
template<int MODE>
__global__ void __launch_bounds__(256, 2)
pk_gemm(const uint8_t* Apk, const uint8_t* __restrict__ Bpk,
        const float* __restrict__ bias,
        float* Cf, uint8_t* Cpk, float* rs,
        int nchunks, long long ldA, long long ldB, int ldc, long long ldCpk,
        int zdiv,
        long long sAo, long long sAi, long long sBo, long long sBi,
        long long sCfO, long long sCfI, long long sCpO, long long sCpI,
        long long rsO, long long rsI, float alpha)
{
    extern __shared__ uint8_t dyn_raw[];
    __shared__ float s_bias[64];
    __shared__ float s_aux[128];

    const int tid = threadIdx.x, wid = tid >> 5, lane = tid & 31;
    const int z = blockIdx.z, zo = z / zdiv, zi = z - zo * zdiv;
    Apk += zo * sAo + zi * sAi;
    Bpk += zo * sBo + zi * sBi;
    if (MODE == 0 || MODE == 3) Cf += zo * sCfO + zi * sCfI;
    if (MODE != 0) Cpk += zo * sCpO + zi * sCpI;
    const long long rs_off = zo * rsO + zi * rsI;

    const long long m0 = (long long)blockIdx.y * 128;
    const long long n0 = (long long)blockIdx.x * 64;

    uint32_t raw = smem_u32(dyn_raw);
    uint32_t base = (raw + 1023u) & ~1023u;
    uint8_t* dsm = dyn_raw + (base - raw);
    uint8_t* smA[2] = { dsm, dsm + 24576 };
    const uint32_t aSu[2] = { base, base + 24576 };
    const uint32_t bSu[2] = { base + 16384, base + 24576 + 16384 };

    if (MODE == 0 || MODE == 1) { if (tid < 64) s_bias[tid] = bias ? bias[n0 + tid] : 0.0f; }
    if (MODE == 2) { if (tid < 128) s_aux[tid] = 0.0f; }
    if (MODE == 3) { if (tid < 128) s_aux[tid] = 1.0f / rs[rs_off + m0 + tid]; }

    float acc[4][2][4];
#pragma unroll
    for (int i = 0; i < 4; i++)
#pragma unroll
        for (int j = 0; j < 2; j++)
#pragma unroll
            for (int e = 0; e < 4; e++) acc[i][j][e] = 0.0f;

    const uint32_t a_row = (uint32_t)((lane & 7) + (lane & 8));
    const uint32_t a_kof = (uint32_t)(((lane >> 4) & 1) * 16);
    const uint32_t b_row = (uint32_t)((lane & 7) + ((lane >> 4) & 1) * 8);
    const uint32_t b_kof = (uint32_t)(((lane >> 3) & 1) * 16);
    const int wm = (wid & 1) * 64;
    const int wn = (wid >> 1) * 16;

    auto prefetch = [&](int s, int c) {
        const uint8_t* Ab = Apk + (long long)c * 128;
#pragma unroll
        for (int i = 0; i < 4; i++) {
            const int idx = i * 256 + tid, row = idx >> 3, g = idx & 7;
            cpa16(aSu[s] + sw128((uint32_t)(row * 128 + g * 16)),
                  Ab + (m0 + row) * ldA + g * 16);
        }
        const uint8_t* Bb = Bpk + (long long)c * 128;
#pragma unroll
        for (int i = 0; i < 2; i++) {
            const int idx = i * 256 + tid, row = idx >> 3, g = idx & 7;
            cpa16(bSu[s] + sw128((uint32_t)(row * 128 + g * 16)),
                  Bb + (n0 + row) * ldB + g * 16);
        }
        asm volatile("cp.async.commit_group;" ::: "memory");
    };

    prefetch(0, 0);
    int cur = 0;
    for (int c = 0; c < nchunks; c++) {
        if (c + 1 < nchunks) {
            prefetch(cur ^ 1, c + 1);
            asm volatile("cp.async.wait_group 1;" ::: "memory");
        } else {
            asm volatile("cp.async.wait_group 0;" ::: "memory");
        }
        __syncthreads();

        if (MODE == 3) {
            // reconstruct normalized fp32 P for this chunk from staged smem (in place)
            const int r = tid >> 1, hh = tid & 1;
            const uint8_t* sa = smA[cur];
            uint4 h0 = *(const uint4*)(sa + sw128((uint32_t)(r * 128 + hh * 32)));
            uint4 h1 = *(const uint4*)(sa + sw128((uint32_t)(r * 128 + hh * 32 + 16)));
            uint4 l0 = *(const uint4*)(sa + sw128((uint32_t)(r * 128 + 64 + hh * 32)));
            uint4 l1 = *(const uint4*)(sa + sw128((uint32_t)(r * 128 + 64 + hh * 32 + 16)));
            const float inv = s_aux[r];
            float o[16];
            combine8(h0, l0, inv, o);
            combine8(h1, l1, inv, o + 8);
            float* dst = Cf + (m0 + r) * (long long)ldc + c * 32 + hh * 16;
            *(float4*)(dst +  0) = make_float4(o[0],  o[1],  o[2],  o[3]);
            *(float4*)(dst +  4) = make_float4(o[4],  o[5],  o[6],  o[7]);
            *(float4*)(dst +  8) = make_float4(o[8],  o[9],  o[10], o[11]);
            *(float4*)(dst + 12) = make_float4(o[12], o[13], o[14], o[15]);
        }

        const uint32_t aS = aSu[cur], bS = bSu[cur];
#pragma unroll
        for (int ks = 0; ks < 2; ks++) {
            uint32_t ah[4][4], al[4][4], bh[2][2], bl[2][2];
#pragma unroll
            for (int mt = 0; mt < 4; mt++) {
                uint32_t off = (uint32_t)(wm + mt * 16 + a_row) * 128 + ks * 32 + a_kof;
                LDSM_X4(ah[mt][0], ah[mt][1], ah[mt][2], ah[mt][3], aS + sw128(off));
            }
            {
                uint32_t r0, r1, r2, r3;
                uint32_t off = (uint32_t)(wn + b_row) * 128 + ks * 32 + b_kof;
                LDSM_X4(r0, r1, r2, r3, bS + sw128(off));
                bh[0][0] = r0; bh[0][1] = r1; bh[1][0] = r2; bh[1][1] = r3;
            }
#pragma unroll
            for (int mt = 0; mt < 4; mt++)
#pragma unroll
                for (int nt = 0; nt < 2; nt++)
                    mma16816(acc[mt][nt], ah[mt], bh[nt]);
            {
                uint32_t r0, r1, r2, r3;
                uint32_t off = (uint32_t)(wn + b_row) * 128 + 64 + ks * 32 + b_kof;
                LDSM_X4(r0, r1, r2, r3, bS + sw128(off));
                bl[0][0] = r0; bl[0][1] = r1; bl[1][0] = r2; bl[1][1] = r3;
            }
#pragma unroll
            for (int mt = 0; mt < 4; mt++)
#pragma unroll
                for (int nt = 0; nt < 2; nt++)
                    mma16816(acc[mt][nt], ah[mt], bl[nt]);
#pragma unroll
            for (int mt = 0; mt < 4; mt++) {
                uint32_t off = (uint32_t)(wm + mt * 16 + a_row) * 128 + 64 + ks * 32 + a_kof;
                LDSM_X4(al[mt][0], al[mt][1], al[mt][2], al[mt][3], aS + sw128(off));
            }
#pragma unroll
            for (int mt = 0; mt < 4; mt++)
#pragma unroll
                for (int nt = 0; nt < 2; nt++)
                    mma16816(acc[mt][nt], al[mt], bh[nt]);
        }
        __syncthreads();
        cur ^= 1;
    }

    // ---- epilogue ----
    const int g = lane >> 2, t = lane & 3;
    if (MODE == 2) {
#pragma unroll
        for (int mt = 0; mt < 4; mt++) {
            float sum0 = 0.0f, sum1 = 0.0f;
#pragma unroll
            for (int nt = 0; nt < 2; nt++) {
                const int colw = wn + nt * 8 + 2 * t;
                const long long row0 = m0 + wm + mt * 16 + g;
                float e0 = __expf(acc[mt][nt][0] * alpha);
                float e1 = __expf(acc[mt][nt][1] * alpha);
                float e2 = __expf(acc[mt][nt][2] * alpha);
                float e3 = __expf(acc[mt][nt][3] * alpha);
                const long long colg = n0 + colw;
                const long long ch = colg >> 5;
                const int wi = (int)(colg & 31);
                pack_store2(Cpk + row0 * ldCpk + ch * 128 + wi * 2, e0, e1);
                pack_store2(Cpk + (row0 + 8) * ldCpk + ch * 128 + wi * 2, e2, e3);
                sum0 += e0 + e1; sum1 += e2 + e3;
            }
            sum0 += __shfl_xor_sync(0xffffffffu, sum0, 1);
            sum0 += __shfl_xor_sync(0xffffffffu, sum0, 2);
            sum1 += __shfl_xor_sync(0xffffffffu, sum1, 1);
            sum1 += __shfl_xor_sync(0xffffffffu, sum1, 2);
            if (t == 0) {
                atomicAdd(&s_aux[wm + mt * 16 + g], sum0);
                atomicAdd(&s_aux[wm + mt * 16 + g + 8], sum1);
            }
        }
        __syncthreads();
        if (tid < 128)
            atomicAdd(&rs[rs_off + m0 + tid], s_aux[tid]);
    } else if (MODE == 1 || MODE == 3) {
#pragma unroll
        for (int mt = 0; mt < 4; mt++) {
            const float i0 = (MODE == 3) ? s_aux[wm + mt * 16 + g] : 1.0f;
            const float i1 = (MODE == 3) ? s_aux[wm + mt * 16 + g + 8] : 1.0f;
#pragma unroll
            for (int nt = 0; nt < 2; nt++) {
                const int colw = wn + nt * 8 + 2 * t;
                const long long row0 = m0 + wm + mt * 16 + g;
                const float b0 = (MODE == 1) ? s_bias[colw] : 0.0f;
                const float b1 = (MODE == 1) ? s_bias[colw + 1] : 0.0f;
                float v0 = acc[mt][nt][0] * i0 + b0;
                float v1 = acc[mt][nt][1] * i0 + b1;
                float v2 = acc[mt][nt][2] * i1 + b0;
                float v3 = acc[mt][nt][3] * i1 + b1;
                const long long colg = n0 + colw;
                const long long ch = colg >> 5;
                const int wi = (int)(colg & 31);
                pack_store2(Cpk + row0 * ldCpk + ch * 128 + wi * 2, v0, v1);
                pack_store2(Cpk + (row0 + 8) * ldCpk + ch * 128 + wi * 2, v2, v3);
            }
        }
    } else {  // MODE 0: fp32 out + bias
#pragma unroll
        for (int mt = 0; mt < 4; mt++) {
#pragma unroll
            for (int nt = 0; nt < 2; nt++) {
                const int colw = wn + nt * 8 + 2 * t;
                const float b0 = s_bias[colw];
                const float b1 = s_bias[colw + 1];
                const long long row0 = m0 + wm + mt * 16 + g;
                *(float2*)(Cf + row0 * (long long)ldc + n0 + colw) =
                    make_float2(acc[mt][nt][0] + b0, acc[mt][nt][1] + b1);
                *(float2*)(Cf + (row0 + 8) * (long long)ldc + n0 + colw) =
                    make_float2(acc[mt][nt][2] + b0, acc[mt][nt][3] + b1);
            }
        }
    }
}

// ---------------------------------------------------------------------------
// V transpose: vh fp32 [B,L,H,DK] -> vT packed [(b*H+h)][dk][L/32][128B]
// ---------------------------------------------------------------------------
__global__ void __launch_bounds__(256)
transpose_v_pk(const float* __restrict__ vh, uint8_t* __restrict__ vT)
{
    __shared__ float tsm[32][33];
    const int bh = blockIdx.z;
    const int b = bh >> 4, h = bh & 15;
    const int l0 = blockIdx.x * 32;
    const int d0 = blockIdx.y * 32;
    const int tid = threadIdx.x;
    const int tx = tid & 31;
    const int ty = tid >> 5;

    const float* src = vh + ((long long)b * L_ + l0) * HD_ + h * DK_ + d0;
#pragma unroll
    for (int i = 0; i < 32; i += 8)
        tsm[ty + i][tx] = src[(long long)(ty + i) * HD_ + tx];
    __syncthreads();

    const int lp = tid & 15;           // l pair
#pragma unroll
    for (int it = 0; it < 2; it++) {
        const int d = (tid >> 4) + 16 * it;
        uint8_t* p = vT + ((long long)bh * 64 + d0 + d) * (L_ / 32 * 128)
                        + (l0 >> 5) * 128 + lp * 4;
        pack_store2(p, tsm[2 * lp][d], tsm[2 * lp + 1][d]);
    }
}

__global__ void zero_rs(float* __restrict__ rs)
{
    rs[blockIdx.x * 256 + threadIdx.x] = 0.0f;
}

// ---------------------------------------------------------------------------
// LayerNorm + residual
// ---------------------------------------------------------------------------
__global__ void __launch_bounds__(256)
ln_residual(const float* __restrict__ x, const float* __restrict__ res,
            const float* __restrict__ gam, const float* __restrict__ bet,
            float* __restrict__ out)
{
    const long long row = blockIdx.x;
    const float4* x4 = (const float4*)(x   + row * D_);
    const float4* r4 = (const float4*)(res + row * D_);
    const int tid = threadIdx.x;

    float4 v = x4[tid];
    float s  = (v.x + v.y) + (v.z + v.w);
    float sq = (v.x * v.x + v.y * v.y) + (v.z * v.z + v.w * v.w);
#pragma unroll
    for (int o = 16; o > 0; o >>= 1) {
        s  += __shfl_xor_sync(0xffffffffu, s,  o);
        sq += __shfl_xor_sync(0xffffffffu, sq, o);
    }
    __shared__ float ss[8], sqs[8];
    if ((tid & 31) == 0) { ss[tid >> 5] = s; sqs[tid >> 5] = sq; }
    __syncthreads();
    s  = (ss[0]  + ss[1])  + (ss[2]  + ss[3])  + (ss[4]  + ss[5])  + (ss[6]  + ss[7]);
    sq = (sqs[0] + sqs[1]) + (sqs[2] + sqs[3]) + (sqs[4] + sqs[5]) + (sqs[6] + sqs[7]);

    const float mean = s * (1.0f / D_);
    float var = sq * (1.0f / D_) - mean * mean;
    var = fmaxf(var, 0.0f);
    const float rstd = rsqrtf(var + LN_EPS_);

    float4 g  = ((const float4*)gam)[tid];
    float4 bt = ((const float4*)bet)[tid];
    float4 r  = r4[tid];
    float4 o;
    o.x = (v.x - mean) * rstd * g.x + bt.x + r.x;
    o.y = (v.y - mean) * rstd * g.y + bt.y + r.y;
    o.z = (v.z - mean) * rstd * g.z + bt.z + r.z;
    o.w = (v.w - mean) * rstd * g.w + bt.w + r.w;
    ((float4*)(out + row * D_))[tid] = o;
}

// ---------------------------------------------------------------------------
// Launch
// ---------------------------------------------------------------------------
extern "C" void kernel_launch(void* const* d_in, const int* in_sizes, int n_in,
                              void* d_out, int out_size)
{
    (void)in_sizes; (void)n_in; (void)out_size;
    const float* q  = (const float*)d_in[0];
    const float* k  = (const float*)d_in[1];
    const float* v  = (const float*)d_in[2];
    const float* wq = (const float*)d_in[3];
    const float* bq = (const float*)d_in[4];
    const float* wk = (const float*)d_in[5];
    const float* bk = (const float*)d_in[6];
    const float* wv = (const float*)d_in[7];
    const float* bv = (const float*)d_in[8];
    const float* wo = (const float*)d_in[9];
    const float* bo = (const float*)d_in[10];
    const float* lg = (const float*)d_in[11];
    const float* lb = (const float*)d_in[12];

    float* out  = (float*)d_out;
    float* attn = out + (long long)B_ * L_ * D_;
    uint8_t* attn_b = (uint8_t*)attn;

    uint8_t *qpk, *kpk, *vpk, *wqpk, *wkpk, *wvpk, *wopk, *qhpk, *khpk, *vTpk, *oapk;
    float *vh, *op, *rs;
    cudaGetSymbolAddress((void**)&qpk,  g_qpk);
    cudaGetSymbolAddress((void**)&kpk,  g_kpk);
    cudaGetSymbolAddress((void**)&vpk,  g_vpk);
    cudaGetSymbolAddress((void**)&wqpk, g_wqpk);
    cudaGetSymbolAddress((void**)&wkpk, g_wkpk);
    cudaGetSymbolAddress((void**)&wvpk, g_wvpk);
    cudaGetSymbolAddress((void**)&wopk, g_wopk);
    cudaGetSymbolAddress((void**)&qhpk, g_qhpk);
    cudaGetSymbolAddress((void**)&khpk, g_khpk);
    cudaGetSymbolAddress((void**)&vTpk, g_vTpk);
    cudaGetSymbolAddress((void**)&oapk, g_oapk);
    cudaGetSymbolAddress((void**)&vh,   g_vh);
    cudaGetSymbolAddress((void**)&op,   g_op);
    cudaGetSymbolAddress((void**)&rs,   g_rs);

    const int SMEMB = 2 * 24576 + 1024;
    cudaFuncSetAttribute((const void*)pk_gemm<0>, cudaFuncAttributeMaxDynamicSharedMemorySize, SMEMB);
    cudaFuncSetAttribute((const void*)pk_gemm<1>, cudaFuncAttributeMaxDynamicSharedMemorySize, SMEMB);
    cudaFuncSetAttribute((const void*)pk_gemm<2>, cudaFuncAttributeMaxDynamicSharedMemorySize, SMEMB);
    cudaFuncSetAttribute((const void*)pk_gemm<3>, cudaFuncAttributeMaxDynamicSharedMemorySize, SMEMB);

    dim3 blk(256);

    zero_rs<<<NROWS_ATTN / 256, blk>>>(rs);

    // pack inputs + weights
    pack_split<<<MROWS_ * D_ / 4 / 256, blk>>>(q, qpk, D_);
    pack_split<<<MROWS_ * D_ / 4 / 256, blk>>>(k, kpk, D_);
    pack_split<<<MROWS_ * D_ / 4 / 256, blk>>>(v, vpk, D_);
    pack_split<<<HD_ * D_ / 4 / 256, blk>>>(wq, wqpk, D_);
    pack_split<<<HD_ * D_ / 4 / 256, blk>>>(wk, wkpk, D_);
    pack_split<<<HD_ * D_ / 4 / 256, blk>>>(wv, wvpk, D_);
    pack_split<<<D_ * HD_ / 4 / 256, blk>>>(wo, wopk, HD_);

    const long long ld32 = 32 * 128;   // 4096 bytes: K=1024 packed row
    const long long ld64 = 64 * 128;   // 8192 bytes: K=2048 packed row

    // QKV projections (K=1024 -> 32 chunks)
    dim3 gproj(HD_ / 64, MROWS_ / 128, 1);
    pk_gemm<1><<<gproj, blk, SMEMB>>>(qpk, wqpk, bq, nullptr, qhpk, nullptr,
        32, ld32, ld32, 0, ld32, 1,
        0, 0, 0, 0, 0, 0, 0, 0, 0, 0, 1.0f);
    pk_gemm<1><<<gproj, blk, SMEMB>>>(kpk, wkpk, bk, nullptr, khpk, nullptr,
        32, ld32, ld32, 0, ld32, 1,
        0, 0, 0, 0, 0, 0, 0, 0, 0, 0, 1.0f);
    pk_gemm<0><<<gproj, blk, SMEMB>>>(vpk, wvpk, bv, vh, nullptr, nullptr,
        32, ld32, ld32, HD_, 0, 1,
        0, 0, 0, 0, 0, 0, 0, 0, 0, 0, 1.0f);

    transpose_v_pk<<<dim3(L_ / 32, DK_ / 32, B_ * H_), blk>>>(vh, vTpk);

    // Scores: z = b*H+h (zdiv=H -> zo=b, zi=h)
    // A=qh packed, B=kh packed (K=64 -> 2 chunks, chunk base offset = h*2*128 bytes)
    dim3 gsc(L_ / 64, L_ / 128, B_ * H_);
    pk_gemm<2><<<gsc, blk, SMEMB>>>(qhpk, khpk, nullptr, nullptr, attn_b, rs,
        2, ld32, ld32, 0, ld64, H_,
        (long long)L_ * ld32, 256,                      // A: b, h (bytes)
        (long long)L_ * ld32, 256,                      // B: b, h (bytes)
        0, 0,
        (long long)L_ * L_ * 4, (long long)B_ * L_ * L_ * 4,   // Cpk bytes
        (long long)L_, (long long)B_ * L_,              // rs
        0.125f);

    // PV: A = attn packed (in place), B = vT packed; P fp32 written in place;
    // O scaled by 1/rowsum -> oa packed
    dim3 gpv(1, L_ / 128, B_ * H_);
    pk_gemm<3><<<gpv, blk, SMEMB>>>(attn_b, vTpk, nullptr, attn, oapk, rs,
        64, ld64, ld64, L_, ld32, H_,
        (long long)L_ * L_ * 4, (long long)B_ * L_ * L_ * 4,   // A bytes
        (long long)DK_ * ld64 * H_, (long long)DK_ * ld64,     // B: b, h (bytes)
        (long long)L_ * L_, (long long)B_ * L_ * L_,           // Cf (P) elems
        (long long)L_ * ld32, 256,                             // Cpk (oa): b rows, h cols
        (long long)L_, (long long)B_ * L_,
        1.0f);

    // Output projection (K=1024 -> 32 chunks)
    dim3 gop(D_ / 64, MROWS_ / 128, 1);
    pk_gemm<0><<<gop, blk, SMEMB>>>(oapk, wopk, bo, op, nullptr, nullptr,
        32, ld32, ld32, D_, 0, 1,
        0, 0, 0, 0, 0, 0, 0, 0, 0, 0, 1.0f);

    // LayerNorm + residual
    ln_residual<<<MROWS_, blk>>>(op, q, lg, lb, out);
}